// round 15
// baseline (speedup 1.0000x reference)
#include <cuda_runtime.h>
#include <cuda_fp16.h>
#include <cstdint>

// Problem constants
#define B_   4
#define T_   2048
#define C_   2048
#define H_   16
#define HKV_ 4
#define REP_ 4
#define D_   128
#define M_   (B_*T_)   // 8192 rows
#define K2C  (C_/2)    // 1024 half2 words along K

// q scale: 1/sqrt(D) * log2(e)  (softmax done in exp2 domain)
#define QSCALE (0.088388347648318447f * 1.4426950408889634f)

// Scratch (device globals — no allocation allowed)
__device__ __half   g_xh[(size_t)M_ * C_];                 // x as fp16
__device__ __half   g_qh[(size_t)M_ * H_ * D_];            // normed+roped q
__device__ __half   g_kh[(size_t)M_ * HKV_ * D_];
__device__ uint32_t g_vh[(size_t)B_ * HKV_ * D_ * (T_/2)]; // V as [bk][d][t2] half2
__device__ __half   g_yh[(size_t)M_ * C_];                 // attention out
__device__ uint32_t g_wqt[(size_t)(H_ * D_) * K2C];        // W^T as [n][k2] half2
__device__ uint32_t g_wkt[(size_t)(HKV_ * D_) * K2C];
__device__ uint32_t g_wvt[(size_t)(HKV_ * D_) * K2C];
__device__ uint32_t g_wct[(size_t)C_ * K2C];
__device__ int      g_cnt[64];   // per 128-row block: flash arrivals (32 = done)

// ============================================================================
// Helpers
// ============================================================================
__device__ __forceinline__ uint32_t smem_u32(const void* p) {
    uint32_t a;
    asm("{ .reg .u64 t; cvta.to.shared.u64 t, %1; cvt.u32.u64 %0, t; }" : "=r"(a) : "l"(p));
    return a;
}
__device__ __forceinline__ uint32_t h2u(__half2 h) {
    return *reinterpret_cast<uint32_t*>(&h);
}
__device__ __forceinline__ uint32_t ex2_f16x2(uint32_t x) {
    uint32_t r; asm("ex2.approx.f16x2 %0, %1;" : "=r"(r) : "r"(x)); return r;
}
#define CP_ASYNC16(dst_u32, src_ptr) \
    asm volatile("cp.async.cg.shared.global [%0], [%1], 16;" \
                 :: "r"(dst_u32), "l"(src_ptr) : "memory")
#define CP_COMMIT() asm volatile("cp.async.commit_group;" ::: "memory")
#define CP_WAIT2()  asm volatile("cp.async.wait_group 2;" ::: "memory")
#define CP_WAIT0()  asm volatile("cp.async.wait_group 0;" ::: "memory")

__device__ __forceinline__ void mma_f16(
    float& c0, float& c1, float& c2, float& c3,
    uint32_t a0, uint32_t a1, uint32_t a2, uint32_t a3,
    uint32_t b0, uint32_t b1)
{
    asm volatile(
        "mma.sync.aligned.m16n8k16.row.col.f32.f16.f16.f32 "
        "{%0,%1,%2,%3}, {%4,%5,%6,%7}, {%8,%9}, {%0,%1,%2,%3};"
        : "+f"(c0), "+f"(c1), "+f"(c2), "+f"(c3)
        : "r"(a0), "r"(a1), "r"(a2), "r"(a3), "r"(b0), "r"(b1));
}
__device__ __forceinline__ void ldsm4(
    uint32_t& r0, uint32_t& r1, uint32_t& r2, uint32_t& r3, uint32_t a)
{
    asm volatile("ldmatrix.sync.aligned.m8n8.x4.shared.b16 {%0,%1,%2,%3}, [%4];"
                 : "=r"(r0), "=r"(r1), "=r"(r2), "=r"(r3) : "r"(a));
}
__device__ __forceinline__ void store2(float* p, float a, float b) {
    *(float2*)p = make_float2(a, b);
}
__device__ __forceinline__ void store2(__half* p, float a, float b) {
    *(uint32_t*)p = h2u(__floats2half2_rn(a, b));
}

// ============================================================================
// Merged prep kernel: bids 0..16383 convert x fp32->fp16 (bid 0 also zeroes
// the flash counters); bids 16384..21503 transpose weights to [N][K/2].
// ============================================================================
__global__ __launch_bounds__(256) void prep_kernel(
    const float4* __restrict__ x4, uint2* __restrict__ xh4,
    const float* __restrict__ Wq, const float* __restrict__ Wk,
    const float* __restrict__ Wv, const float* __restrict__ Wc)
{
    const int tid = threadIdx.x;
    int bid = blockIdx.x;

    if (bid < 16384) {
        if (bid == 0 && tid < 64) g_cnt[tid] = 0;
        int i = bid * 256 + tid;
        float4 v = x4[i];
        uint2 u;
        u.x = h2u(__floats2half2_rn(v.x, v.y));
        u.y = h2u(__floats2half2_rn(v.z, v.w));
        xh4[i] = u;
        return;
    }
    bid -= 16384;

    const float* W; uint32_t* Wt2; int N, l;
    if (bid < 2048)      { W = Wq; Wt2 = g_wqt; N = 2048; l = bid; }
    else if (bid < 2560) { W = Wk; Wt2 = g_wkt; N = 512;  l = bid - 2048; }
    else if (bid < 3072) { W = Wv; Wt2 = g_wvt; N = 512;  l = bid - 2560; }
    else                 { W = Wc; Wt2 = g_wct; N = 2048; l = bid - 3072; }

    __shared__ uint32_t ts[32][33];
    const int nx = N / 32;
    const int n0 = (l % nx) * 32, k20 = (l / nx) * 32;
    const int tx = tid & 31, ty = tid >> 5;
    #pragma unroll
    for (int i = 0; i < 4; i++) {
        int k2 = k20 + ty + i * 8;
        float a = W[(size_t)(2 * k2) * N + n0 + tx];
        float b = W[(size_t)(2 * k2 + 1) * N + n0 + tx];
        ts[ty + i * 8][tx] = h2u(__floats2half2_rn(a, b));
    }
    __syncthreads();
    #pragma unroll
    for (int i = 0; i < 4; i++)
        Wt2[(size_t)(n0 + ty + i * 8) * K2C + k20 + tx] = ts[tx][ty + i * 8];
}

// ============================================================================
// 128-thread GEMM machinery: 128x128 CTA, BK=32 halves, 4 warps (2Mx2N),
// warp tile 64x64, m16n8k16 via ldmatrix, 4-stage cp.async.  [proven config]
// ============================================================================
#define BM 128
#define BN 128
#define GST 4
#define ASW 20
#define BS_OFF (BM * ASW)               // 2560 words
#define STAGE_WORDS (2 * BM * ASW)      // 5120 words
#define GEMM_SMEM (GST * STAGE_WORDS * 4)  // 81920 B

__device__ __forceinline__ void gemm_issue_stage(
    uint32_t stage_u, const __half* __restrict__ Ab,
    const uint32_t* __restrict__ Bb2, int K, int kt, int tid)
{
    const int K2 = K / 2;
    const int rr = tid >> 2;
    const int c4 = tid & 3;
    const __half* ga = Ab + (size_t)rr * K + kt * 32 + c4 * 8;
    uint32_t sa = stage_u + (uint32_t)(rr * ASW + c4 * 4) * 4;
    #pragma unroll
    for (int p = 0; p < 4; p++)
        CP_ASYNC16(sa + (uint32_t)(p * 32 * ASW) * 4u, ga + (size_t)(p * 32) * K);
    const uint32_t* gb = Bb2 + (size_t)rr * K2 + kt * 16 + c4 * 4;
    uint32_t sb = stage_u + (uint32_t)(BS_OFF + rr * ASW + c4 * 4) * 4;
    #pragma unroll
    for (int p = 0; p < 4; p++)
        CP_ASYNC16(sb + (uint32_t)(p * 32 * ASW) * 4u, gb + (size_t)(p * 32) * K2);
}

__device__ __forceinline__ void gemm_mainloop(
    uint32_t* sw, const __half* Ab, const uint32_t* Bb2, int K,
    float acc[4][8][4], int tid)
{
    const int lane  = tid & 31;
    const int wid   = tid >> 5;
    const int warpM = wid & 1;
    const int warpN = wid >> 1;
    const int KT = K / 32;
    const uint32_t smem_base = smem_u32(sw);

    #pragma unroll
    for (int s = 0; s < GST - 1; s++) {
        gemm_issue_stage(smem_base + s * STAGE_WORDS * 4, Ab, Bb2, K, s, tid);
        CP_COMMIT();
    }

    const uint32_t aoff = (uint32_t)((warpM * 64 + (lane & 15)) * ASW + (lane >> 4) * 4) * 4;
    const uint32_t boff = (uint32_t)((BS_OFF + (warpN * 64 + (lane & 7) + ((lane >> 4) << 3)) * ASW)
                                     + ((lane >> 3) & 1) * 4) * 4;

    for (int kt = 0; kt < KT; kt++) {
        const int buf = kt & (GST - 1);
        CP_WAIT2();
        __syncthreads();

        const int nxt = kt + GST - 1;
        if (nxt < KT)
            gemm_issue_stage(smem_base + (nxt & (GST - 1)) * STAGE_WORDS * 4,
                             Ab, Bb2, K, nxt, tid);
        CP_COMMIT();

        const uint32_t stage_u = smem_base + buf * STAGE_WORDS * 4;
        #pragma unroll
        for (int ks = 0; ks < 2; ks++) {
            uint32_t af[4][4], bf[8][2];
            #pragma unroll
            for (int mt = 0; mt < 4; mt++)
                ldsm4(af[mt][0], af[mt][1], af[mt][2], af[mt][3],
                      stage_u + aoff + (uint32_t)(mt * 16 * ASW + ks * 8) * 4);
            #pragma unroll
            for (int np = 0; np < 4; np++)
                ldsm4(bf[2*np][0], bf[2*np][1], bf[2*np+1][0], bf[2*np+1][1],
                      stage_u + boff + (uint32_t)(np * 16 * ASW + ks * 8) * 4);
            #pragma unroll
            for (int mt = 0; mt < 4; mt++)
                #pragma unroll
                for (int nt = 0; nt < 8; nt++)
                    mma_f16(acc[mt][nt][0], acc[mt][nt][1], acc[mt][nt][2], acc[mt][nt][3],
                            af[mt][0], af[mt][1], af[mt][2], af[mt][3],
                            bf[nt][0], bf[nt][1]);
        }
        __syncthreads();
    }
}

// ============================================================================
// Fused QKV GEMM: grid (24, 64). x-blocks 0..15 -> q (norm+rope, scaled),
// 16..19 -> k (norm+rope), 20..23 -> v (transposed directly to [bk][d][t2]).
// ============================================================================
__global__ __launch_bounds__(128, 2) void qkv_gemm_kernel(
    const __half* __restrict__ A,
    const uint32_t* __restrict__ Wq2, const uint32_t* __restrict__ Wk2,
    const uint32_t* __restrict__ Wv2,
    __half* __restrict__ Qh, __half* __restrict__ Kh, uint32_t* __restrict__ Vt2,
    const float* __restrict__ fc)
{
    extern __shared__ uint32_t sw[];
    const int bx  = blockIdx.x;
    const int by  = blockIdx.y;
    const int tid = threadIdx.x;
    const int lane = tid & 31, wid = tid >> 5;
    const int warpM = wid & 1, warpN = wid >> 1;

    const uint32_t* B2;
    int ncol;
    bool norm;
    float scale = 1.0f;
    if (bx < 16)      { B2 = Wq2; ncol = bx;      norm = true;  scale = QSCALE; }
    else if (bx < 20) { B2 = Wk2; ncol = bx - 16; norm = true;  }
    else              { B2 = Wv2; ncol = bx - 20; norm = false; }

    const __half*   Ab  = A  + (size_t)by * BM * C_;
    const uint32_t* Bb2 = B2 + (size_t)ncol * BN * K2C;

    float acc[4][8][4];
    #pragma unroll
    for (int i = 0; i < 4; i++)
        #pragma unroll
        for (int j = 0; j < 8; j++)
            #pragma unroll
            for (int c = 0; c < 4; c++) acc[i][j][c] = 0.f;

    gemm_mainloop(sw, Ab, Bb2, C_, acc, tid);

    const int r = lane >> 2, c = lane & 3;
    const int ccol0 = warpN * 64 + c * 2;

    if (!norm) {
        // ---- V epilogue: transpose to [bk][d][t2] via smem (stride 129) ----
        __half* vs = (__half*)sw;   // 128 x 129 halves = 33024 B (smem free now)
        #pragma unroll
        for (int mt = 0; mt < 4; mt++) {
            const int rr = warpM * 64 + mt * 16 + r;
            #pragma unroll
            for (int nt = 0; nt < 8; nt++) {
                const int cc = ccol0 + nt * 8;
                vs[rr * 129 + cc]           = __float2half_rn(acc[mt][nt][0]);
                vs[rr * 129 + cc + 1]       = __float2half_rn(acc[mt][nt][1]);
                vs[(rr + 8) * 129 + cc]     = __float2half_rn(acc[mt][nt][2]);
                vs[(rr + 8) * 129 + cc + 1] = __float2half_rn(acc[mt][nt][3]);
            }
        }
        __syncthreads();

        const int b = by >> 4;   // batch, 16 row-blocks per batch
        uint32_t* vb = Vt2 + (size_t)(b * HKV_ + ncol) * D_ * (T_ / 2)
                           + (size_t)(by & 15) * 64;
        for (int i = tid; i < 128 * 64; i += 128) {
            const int lt2 = i & 63;
            const int d   = i >> 6;
            __half lo = vs[(2 * lt2)     * 129 + d];
            __half hi = vs[(2 * lt2 + 1) * 129 + d];
            vb[(size_t)d * (T_ / 2) + lt2] = h2u(__halves2half2(lo, hi));
        }
        return;
    }

    const int N = (bx < 16) ? (H_ * D_) : (HKV_ * D_);
    __half* Cb = ((bx < 16) ? Qh : Kh) + (size_t)by * BM * N + (size_t)ncol * BN;

    // --- fused RMSNorm + RoPE epilogue (BN == D == 128: one head per tile) ---
    float* red = (float*)sw;
    #pragma unroll
    for (int mt = 0; mt < 4; mt++) {
        float p0 = 0.f, p1 = 0.f;
        #pragma unroll
        for (int nt = 0; nt < 8; nt++) {
            p0 += acc[mt][nt][0] * acc[mt][nt][0] + acc[mt][nt][1] * acc[mt][nt][1];
            p1 += acc[mt][nt][2] * acc[mt][nt][2] + acc[mt][nt][3] * acc[mt][nt][3];
        }
        p0 += __shfl_xor_sync(0xffffffffu, p0, 1);
        p0 += __shfl_xor_sync(0xffffffffu, p0, 2);
        p1 += __shfl_xor_sync(0xffffffffu, p1, 1);
        p1 += __shfl_xor_sync(0xffffffffu, p1, 2);
        if (c == 0) {
            const int row = warpM * 64 + mt * 16 + r;
            red[warpN * 128 + row]     = p0;
            red[warpN * 128 + row + 8] = p1;
        }
    }
    __syncthreads();

    #pragma unroll
    for (int mt = 0; mt < 4; mt++) {
        const int row0 = warpM * 64 + mt * 16 + r;
        const int row1 = row0 + 8;
        const float ms0 = (red[row0] + red[128 + row0]) * (1.f / (float)D_);
        const float ms1 = (red[row1] + red[128 + row1]) * (1.f / (float)D_);
        const float ri0 = rsqrtf(ms0 + 1e-6f) * scale;
        const float ri1 = rsqrtf(ms1 + 1e-6f) * scale;
        const int t0 = (by * BM + row0) & (T_ - 1);
        const int t1 = (by * BM + row1) & (T_ - 1);
        #pragma unroll
        for (int nt = 0; nt < 8; nt++) {
            const int cc = ccol0 + nt * 8;
            float2 cs0 = *(const float2*)(fc + (size_t)t0 * D_ + cc);
            float2 cs1 = *(const float2*)(fc + (size_t)t1 * D_ + cc);
            float a0 = acc[mt][nt][0], a1 = acc[mt][nt][1];
            float b0 = acc[mt][nt][2], b1 = acc[mt][nt][3];
            store2(Cb + (size_t)row0 * N + cc,
                   (a0 * cs0.x - a1 * cs0.y) * ri0, (a0 * cs0.y + a1 * cs0.x) * ri0);
            store2(Cb + (size_t)row1 * N + cc,
                   (b0 * cs1.x - b1 * cs1.y) * ri1, (b0 * cs1.y + b1 * cs1.x) * ri1);
        }
    }
}

// ============================================================================
// Fused flash-attention + output-projection kernel, 128 threads / CTA
// (2 CTAs/SM). Flash CTAs cover 64 q-rows (4 warps x 16 rows).
// grid = 3072:
//   bid 0..2047   : flash, qt64 = 31 - (bid>>6) (LPT), bh = bid&63.
//   bid 2048..3071: Wc GEMM 128x128, LPT order; waits g_cnt[by]==32.
// ============================================================================
#define QKW 68
#define VSW 36
#define VBUF (128 * VSW)
#define FQ_WORDS (64 * QKW)                                  // 4352
#define FLASH_WORDS (FQ_WORDS + 2 * 64 * QKW + 2 * VBUF)     // 22272 words
#define FLASH_SMEM  (FLASH_WORDS * 4)                        // 89088 B

__global__ __launch_bounds__(128, 2) void flash_wc_kernel(
    const __half* __restrict__ Qh, const __half* __restrict__ Kh,
    const uint32_t* __restrict__ Vt2, __half* __restrict__ Oh,
    const uint32_t* __restrict__ Wc2, float* __restrict__ Out)
{
    extern __shared__ uint32_t sw[];
    const int tid  = threadIdx.x;
    const int lane = tid & 31, wid = tid >> 5;

    if (blockIdx.x < 2048) {
        // ------------------------- flash role (64 q-rows) -------------------------
        const int qt64 = 31 - (int)(blockIdx.x >> 6);   // LPT: heavy first
        const int bh   = blockIdx.x & 63;
        uint32_t* Qs = sw;                       // 64 x 68
        uint32_t* Ks = sw + FQ_WORDS;            // 2 x 64 x 68
        uint32_t* Vs = Ks + 2 * 64 * QKW;        // 2 x 128 x 36

        const int r = lane >> 2, c = lane & 3;
        const int b = bh / H_, h = bh % H_;
        const int kvh = h / REP_;
        const int m0 = qt64 * 64;
        const int wrow = m0 + wid * 16;
        const uint32_t qu = smem_u32(Qs);
        const uint32_t ku = smem_u32(Ks);
        const uint32_t vu = smem_u32(Vs);

        const __half* Qb = Qh + ((size_t)(b * T_ + m0) * H_ + h) * D_;
        const __half* Kb = Kh + ((size_t)b * T_ * HKV_ + kvh) * D_;
        const uint32_t* Vb = Vt2 + (size_t)(b * HKV_ + kvh) * D_ * (T_ / 2);

        for (int i = tid; i < 64 * 16; i += 128) {
            int row = i >> 4, c4 = i & 15;
            CP_ASYNC16(qu + (uint32_t)(row * QKW + c4 * 4) * 4,
                       Qb + (size_t)row * (H_ * D_) + c4 * 8);
            CP_ASYNC16(ku + (uint32_t)(row * QKW + c4 * 4) * 4,
                       Kb + (size_t)row * (HKV_ * D_) + c4 * 8);
        }
        for (int i = tid; i < 128 * 8; i += 128) {
            int row = i >> 3, c4 = i & 7;
            CP_ASYNC16(vu + (uint32_t)(row * VSW + c4 * 4) * 4,
                       Vb + (size_t)row * (T_ / 2) + c4 * 4);
        }
        CP_COMMIT();

        const uint32_t qoff = (uint32_t)((wid * 16 + (lane & 15)) * QKW + (lane >> 4) * 4) * 4;
        const uint32_t koff = (uint32_t)(((lane & 7) + ((lane >> 4) << 3)) * QKW
                                         + ((lane >> 3) & 1) * 4) * 4;
        const uint32_t voff = (uint32_t)(((lane & 7) + ((lane >> 4) << 3)) * VSW
                                         + ((lane >> 3) & 1) * 4) * 4;

        uint32_t qf[8][4];
        float oa[16][4];
        #pragma unroll
        for (int db = 0; db < 16; db++)
            oa[db][0] = oa[db][1] = oa[db][2] = oa[db][3] = 0.f;
        float m0r = -1e30f, m1r = -1e30f, l0 = 0.f, l1 = 0.f;

        const int nT = qt64 + 1;   // 64-key tiles

        for (int j = 0; j < nT; j++) {
            const int buf = j & 1;
            const int n0 = j * 64;
            CP_WAIT0();
            __syncthreads();

            if (j + 1 < nT) {
                const int nb2 = buf ^ 1;
                for (int i = tid; i < 64 * 16; i += 128) {
                    int row = i >> 4, c4 = i & 15;
                    CP_ASYNC16(ku + (uint32_t)(nb2 * 64 * QKW + row * QKW + c4 * 4) * 4,
                               Kb + (size_t)((j + 1) * 64 + row) * (HKV_ * D_) + c4 * 8);
                }
                for (int i = tid; i < 128 * 8; i += 128) {
                    int row = i >> 3, c4 = i & 7;
                    CP_ASYNC16(vu + (uint32_t)(nb2 * VBUF + row * VSW + c4 * 4) * 4,
                               Vb + (size_t)row * (T_ / 2) + (j + 1) * 32 + c4 * 4);
                }
                CP_COMMIT();
            }

            if (j == 0) {
                #pragma unroll
                for (int ks = 0; ks < 8; ks++)
                    ldsm4(qf[ks][0], qf[ks][1], qf[ks][2], qf[ks][3],
                          qu + qoff + (uint32_t)(ks * 8) * 4);
            }

            const uint32_t kbase = ku + (uint32_t)(buf * 64 * QKW) * 4 + koff;
            float s[8][4];
            #pragma unroll
            for (int nb = 0; nb < 8; nb++)
                s[nb][0] = s[nb][1] = s[nb][2] = s[nb][3] = 0.f;
            #pragma unroll
            for (int ks = 0; ks < 8; ks++) {
                uint32_t kf[8][2];
                #pragma unroll
                for (int np = 0; np < 4; np++)
                    ldsm4(kf[2*np][0], kf[2*np][1], kf[2*np+1][0], kf[2*np+1][1],
                          kbase + (uint32_t)(np * 16 * QKW + ks * 8) * 4);
                #pragma unroll
                for (int nb = 0; nb < 8; nb++)
                    mma_f16(s[nb][0], s[nb][1], s[nb][2], s[nb][3],
                            qf[ks][0], qf[ks][1], qf[ks][2], qf[ks][3],
                            kf[nb][0], kf[nb][1]);
            }

            if (n0 + 63 > wrow) {
                #pragma unroll
                for (int nb = 0; nb < 8; nb++) {
                    int col = n0 + nb * 8 + 2 * c;
                    if (col     > wrow + r)     s[nb][0] = -1e30f;
                    if (col + 1 > wrow + r)     s[nb][1] = -1e30f;
                    if (col     > wrow + r + 8) s[nb][2] = -1e30f;
                    if (col + 1 > wrow + r + 8) s[nb][3] = -1e30f;
                }
            }

            float mx0 = -1e30f, mx1 = -1e30f;
            #pragma unroll
            for (int nb = 0; nb < 8; nb++) {
                mx0 = fmaxf(mx0, fmaxf(s[nb][0], s[nb][1]));
                mx1 = fmaxf(mx1, fmaxf(s[nb][2], s[nb][3]));
            }
            mx0 = fmaxf(mx0, __shfl_xor_sync(0xffffffffu, mx0, 1));
            mx0 = fmaxf(mx0, __shfl_xor_sync(0xffffffffu, mx0, 2));
            mx1 = fmaxf(mx1, __shfl_xor_sync(0xffffffffu, mx1, 1));
            mx1 = fmaxf(mx1, __shfl_xor_sync(0xffffffffu, mx1, 2));
            float mn0 = fmaxf(m0r, mx0), mn1 = fmaxf(m1r, mx1);
            float a0 = exp2f(m0r - mn0), a1 = exp2f(m1r - mn1);

            // p = exp2(s - m) in fp16x2 — output IS the PV A-fragment
            uint32_t pf[8][2];
            float ls0 = 0.f, ls1 = 0.f;
            #pragma unroll
            for (int nb = 0; nb < 8; nb++) {
                uint32_t p01 = ex2_f16x2(h2u(__floats2half2_rn(s[nb][0] - mn0, s[nb][1] - mn0)));
                uint32_t p23 = ex2_f16x2(h2u(__floats2half2_rn(s[nb][2] - mn1, s[nb][3] - mn1)));
                pf[nb][0] = p01;
                pf[nb][1] = p23;
                float2 f01 = __half22float2(*(__half2*)&p01);
                float2 f23 = __half22float2(*(__half2*)&p23);
                ls0 += f01.x + f01.y;
                ls1 += f23.x + f23.y;
            }
            ls0 += __shfl_xor_sync(0xffffffffu, ls0, 1);
            ls0 += __shfl_xor_sync(0xffffffffu, ls0, 2);
            ls1 += __shfl_xor_sync(0xffffffffu, ls1, 1);
            ls1 += __shfl_xor_sync(0xffffffffu, ls1, 2);
            l0 = l0 * a0 + ls0; l1 = l1 * a1 + ls1;
            m0r = mn0; m1r = mn1;
            #pragma unroll
            for (int db = 0; db < 16; db++) {
                oa[db][0] *= a0; oa[db][1] *= a0;
                oa[db][2] *= a1; oa[db][3] *= a1;
            }

            const uint32_t vbase = vu + (uint32_t)(buf * VBUF) * 4 + voff;
            #pragma unroll
            for (int kb2 = 0; kb2 < 4; kb2++) {
                uint32_t pa0 = pf[2*kb2][0];
                uint32_t pa1 = pf[2*kb2][1];
                uint32_t pa2 = pf[2*kb2+1][0];
                uint32_t pa3 = pf[2*kb2+1][1];
                #pragma unroll
                for (int dp = 0; dp < 8; dp++) {
                    uint32_t v0, v1, v2, v3;
                    ldsm4(v0, v1, v2, v3,
                          vbase + (uint32_t)(dp * 16 * VSW + kb2 * 8) * 4);
                    mma_f16(oa[2*dp][0], oa[2*dp][1], oa[2*dp][2], oa[2*dp][3],
                            pa0, pa1, pa2, pa3, v0, v1);
                    mma_f16(oa[2*dp+1][0], oa[2*dp+1][1], oa[2*dp+1][2], oa[2*dp+1][3],
                            pa0, pa1, pa2, pa3, v2, v3);
                }
            }
        }

        const float i0 = 1.f / l0, i1 = 1.f / l1;
        const int row_g = m0 + wid * 16 + r;
        __half* Ob = Oh + ((size_t)(b * T_ + row_g) * H_ + h) * D_;
        #pragma unroll
        for (int db = 0; db < 16; db++) {
            *(uint32_t*)(Ob + db * 8 + 2 * c) =
                h2u(__floats2half2_rn(oa[db][0] * i0, oa[db][1] * i0));
            *(uint32_t*)(Ob + (size_t)8 * H_ * D_ + db * 8 + 2 * c) =
                h2u(__floats2half2_rn(oa[db][2] * i1, oa[db][3] * i1));
        }

        __threadfence();
        __syncthreads();
        if (tid == 0) atomicAdd(&g_cnt[b * 16 + (qt64 >> 1)], 1);

    } else {
        // --------- Wc GEMM role: proven 128-thread 128x128 mainloop ---------
        const int wcid = (int)blockIdx.x - 2048;   // 0..1023
        const int qt  = 15 - (wcid >> 6);          // match flash readiness order
        const int rem = wcid & 63;
        const int b   = rem >> 4;
        const int bx  = rem & 15;
        const int by  = b * 16 + qt;

        if (tid == 0) {
            while (atomicAdd(&g_cnt[by], 0) < 32) __nanosleep(256);
        }
        __syncthreads();

        const __half*   Ab  = Oh  + (size_t)by * BM * C_;
        const uint32_t* Bb2 = Wc2 + (size_t)bx * BN * K2C;

        float acc[4][8][4];
        #pragma unroll
        for (int i = 0; i < 4; i++)
            #pragma unroll
            for (int j = 0; j < 8; j++)
                #pragma unroll
                for (int cc = 0; cc < 4; cc++) acc[i][j][cc] = 0.f;

        gemm_mainloop(sw, Ab, Bb2, C_, acc, tid);

        float* Cb = Out + (size_t)by * BM * C_ + (size_t)bx * BN;
        const int r = lane >> 2, c = lane & 3;
        const int warpM = wid & 1, warpN = wid >> 1;
        const int ccol0 = warpN * 64 + c * 2;
        #pragma unroll
        for (int mt = 0; mt < 4; mt++) {
            const int rr = warpM * 64 + mt * 16 + r;
            #pragma unroll
            for (int nt = 0; nt < 8; nt++) {
                const int cc = ccol0 + nt * 8;
                store2(Cb + (size_t)rr * C_ + cc,       acc[mt][nt][0], acc[mt][nt][1]);
                store2(Cb + (size_t)(rr + 8) * C_ + cc, acc[mt][nt][2], acc[mt][nt][3]);
            }
        }
    }
}

// ============================================================================
// Launch
// ============================================================================
extern "C" void kernel_launch(void* const* d_in, const int* in_sizes, int n_in,
                              void* d_out, int out_size)
{
    (void)in_sizes; (void)n_in; (void)out_size;
    const float* x  = (const float*)d_in[0];
    const float* fc = (const float*)d_in[1];
    const float* Wq = (const float*)d_in[2];
    const float* Wk = (const float*)d_in[3];
    const float* Wv = (const float*)d_in[4];
    const float* Wc = (const float*)d_in[5];
    float* out = (float*)d_out;

    __half *xh, *qh, *kh, *yh;
    uint32_t *vh, *wqt, *wkt, *wvt, *wct;
    cudaGetSymbolAddress((void**)&xh,  g_xh);
    cudaGetSymbolAddress((void**)&qh,  g_qh);
    cudaGetSymbolAddress((void**)&kh,  g_kh);
    cudaGetSymbolAddress((void**)&vh,  g_vh);
    cudaGetSymbolAddress((void**)&yh,  g_yh);
    cudaGetSymbolAddress((void**)&wqt, g_wqt);
    cudaGetSymbolAddress((void**)&wkt, g_wkt);
    cudaGetSymbolAddress((void**)&wvt, g_wvt);
    cudaGetSymbolAddress((void**)&wct, g_wct);

    // Prep: x conversion + all weight transposes + counter zeroing, one launch
    prep_kernel<<<16384 + 5120, 256>>>(
        (const float4*)x, (uint2*)xh, Wq, Wk, Wv, Wc);

    cudaFuncSetAttribute(qkv_gemm_kernel, cudaFuncAttributeMaxDynamicSharedMemorySize, GEMM_SMEM);
    cudaFuncSetAttribute(flash_wc_kernel, cudaFuncAttributeMaxDynamicSharedMemorySize, FLASH_SMEM);

    // Fused QKV projection + RMSNorm/RoPE + direct V transpose epilogue
    qkv_gemm_kernel<<<dim3(24, M_ / BM), 128, GEMM_SMEM>>>(
        xh, wqt, wkt, wvt, qh, kh, vh, fc);

    // Fused flash attention + output projection (128-thread CTAs, 2/SM)
    flash_wc_kernel<<<3072, 128, FLASH_SMEM>>>(qh, kh, vh, yh, wct, out);
}

// round 16
// speedup vs baseline: 1.5061x; 1.5061x over previous
#include <cuda_runtime.h>
#include <cuda_fp16.h>
#include <cstdint>

// Problem constants
#define B_   4
#define T_   2048
#define C_   2048
#define H_   16
#define HKV_ 4
#define REP_ 4
#define D_   128
#define M_   (B_*T_)   // 8192 rows
#define K2C  (C_/2)    // 1024 half2 words along K

// q scale: 1/sqrt(D) * log2(e)  (softmax done in exp2 domain)
#define QSCALE (0.088388347648318447f * 1.4426950408889634f)

// Scratch (device globals — no allocation allowed)
__device__ __half   g_xh[(size_t)M_ * C_];                 // x as fp16
__device__ __half   g_vg[(size_t)M_ * HKV_ * D_];          // raw v (fp16)
__device__ __half   g_qh[(size_t)M_ * H_ * D_];            // normed+roped q
__device__ __half   g_kh[(size_t)M_ * HKV_ * D_];
__device__ uint32_t g_vh[(size_t)B_ * HKV_ * D_ * (T_/2)]; // V as [bk][d][t2] half2
__device__ __half   g_yh[(size_t)M_ * C_];                 // attention out
__device__ uint32_t g_wqt[(size_t)(H_ * D_) * K2C];        // W^T as [n][k2] half2
__device__ uint32_t g_wkt[(size_t)(HKV_ * D_) * K2C];
__device__ uint32_t g_wvt[(size_t)(HKV_ * D_) * K2C];
__device__ uint32_t g_wct[(size_t)C_ * K2C];
__device__ int      g_cnt[64];   // per 128-row block: flash arrivals (32 = done)

// ============================================================================
// Helpers
// ============================================================================
__device__ __forceinline__ uint32_t smem_u32(const void* p) {
    uint32_t a;
    asm("{ .reg .u64 t; cvta.to.shared.u64 t, %1; cvt.u32.u64 %0, t; }" : "=r"(a) : "l"(p));
    return a;
}
__device__ __forceinline__ uint32_t h2u(__half2 h) {
    return *reinterpret_cast<uint32_t*>(&h);
}
__device__ __forceinline__ uint32_t ex2_f16x2(uint32_t x) {
    uint32_t r; asm("ex2.approx.f16x2 %0, %1;" : "=r"(r) : "r"(x)); return r;
}
#define CP_ASYNC16(dst_u32, src_ptr) \
    asm volatile("cp.async.cg.shared.global [%0], [%1], 16;" \
                 :: "r"(dst_u32), "l"(src_ptr) : "memory")
#define CP_COMMIT() asm volatile("cp.async.commit_group;" ::: "memory")
#define CP_WAIT2()  asm volatile("cp.async.wait_group 2;" ::: "memory")
#define CP_WAIT0()  asm volatile("cp.async.wait_group 0;" ::: "memory")

__device__ __forceinline__ void mma_f16(
    float& c0, float& c1, float& c2, float& c3,
    uint32_t a0, uint32_t a1, uint32_t a2, uint32_t a3,
    uint32_t b0, uint32_t b1)
{
    asm volatile(
        "mma.sync.aligned.m16n8k16.row.col.f32.f16.f16.f32 "
        "{%0,%1,%2,%3}, {%4,%5,%6,%7}, {%8,%9}, {%0,%1,%2,%3};"
        : "+f"(c0), "+f"(c1), "+f"(c2), "+f"(c3)
        : "r"(a0), "r"(a1), "r"(a2), "r"(a3), "r"(b0), "r"(b1));
}
__device__ __forceinline__ void ldsm4(
    uint32_t& r0, uint32_t& r1, uint32_t& r2, uint32_t& r3, uint32_t a)
{
    asm volatile("ldmatrix.sync.aligned.m8n8.x4.shared.b16 {%0,%1,%2,%3}, [%4];"
                 : "=r"(r0), "=r"(r1), "=r"(r2), "=r"(r3) : "r"(a));
}
__device__ __forceinline__ void store2(float* p, float a, float b) {
    *(float2*)p = make_float2(a, b);
}
__device__ __forceinline__ void store2(__half* p, float a, float b) {
    *(uint32_t*)p = h2u(__floats2half2_rn(a, b));
}

// ============================================================================
// Merged prep kernel: bids 0..16383 convert x fp32->fp16 (bid 0 also zeroes
// the flash counters); bids 16384..21503 transpose weights to [N][K/2].
// ============================================================================
__global__ __launch_bounds__(256) void prep_kernel(
    const float4* __restrict__ x4, uint2* __restrict__ xh4,
    const float* __restrict__ Wq, const float* __restrict__ Wk,
    const float* __restrict__ Wv, const float* __restrict__ Wc)
{
    const int tid = threadIdx.x;
    int bid = blockIdx.x;

    if (bid < 16384) {
        if (bid == 0 && tid < 64) g_cnt[tid] = 0;
        int i = bid * 256 + tid;
        float4 v = x4[i];
        uint2 u;
        u.x = h2u(__floats2half2_rn(v.x, v.y));
        u.y = h2u(__floats2half2_rn(v.z, v.w));
        xh4[i] = u;
        return;
    }
    bid -= 16384;

    const float* W; uint32_t* Wt2; int N, l;
    if (bid < 2048)      { W = Wq; Wt2 = g_wqt; N = 2048; l = bid; }
    else if (bid < 2560) { W = Wk; Wt2 = g_wkt; N = 512;  l = bid - 2048; }
    else if (bid < 3072) { W = Wv; Wt2 = g_wvt; N = 512;  l = bid - 2560; }
    else                 { W = Wc; Wt2 = g_wct; N = 2048; l = bid - 3072; }

    __shared__ uint32_t ts[32][33];
    const int nx = N / 32;
    const int n0 = (l % nx) * 32, k20 = (l / nx) * 32;
    const int tx = tid & 31, ty = tid >> 5;
    #pragma unroll
    for (int i = 0; i < 4; i++) {
        int k2 = k20 + ty + i * 8;
        float a = W[(size_t)(2 * k2) * N + n0 + tx];
        float b = W[(size_t)(2 * k2 + 1) * N + n0 + tx];
        ts[ty + i * 8][tx] = h2u(__floats2half2_rn(a, b));
    }
    __syncthreads();
    #pragma unroll
    for (int i = 0; i < 4; i++)
        Wt2[(size_t)(n0 + ty + i * 8) * K2C + k20 + tx] = ts[tx][ty + i * 8];
}

// v transpose (B,T,HKV,D fp16 -> [bk][d][T/2] half2, pairs along T)
__global__ __launch_bounds__(256) void conv_v_kernel(
    const __half* __restrict__ V, uint32_t* __restrict__ Vt2)
{
    int idx = blockIdx.x * 256 + threadIdx.x;
    const int total = B_ * HKV_ * D_ * (T_ / 2);
    if (idx < total) {
        int t2  = idx & (T_ / 2 - 1);
        int d   = (idx >> 10) & (D_ - 1);
        int kvh = (idx >> 17) & (HKV_ - 1);
        int b   = idx >> 19;
        size_t src = ((size_t)(b * T_ + 2 * t2) * HKV_ + kvh) * D_ + d;
        Vt2[idx] = h2u(__halves2half2(V[src], V[src + (size_t)HKV_ * D_]));
    }
}

// ============================================================================
// 128-thread GEMM machinery: 128x128 CTA, BK=32 halves, 4 warps (2Mx2N),
// warp tile 64x64, m16n8k16 via ldmatrix, 4-stage cp.async.  [proven config]
// ============================================================================
#define BM 128
#define BN 128
#define GST 4
#define ASW 20
#define BS_OFF (BM * ASW)               // 2560 words
#define STAGE_WORDS (2 * BM * ASW)      // 5120 words
#define GEMM_SMEM (GST * STAGE_WORDS * 4)  // 81920 B

__device__ __forceinline__ void gemm_issue_stage(
    uint32_t stage_u, const __half* __restrict__ Ab,
    const uint32_t* __restrict__ Bb2, int K, int kt, int tid)
{
    const int K2 = K / 2;
    const int rr = tid >> 2;
    const int c4 = tid & 3;
    const __half* ga = Ab + (size_t)rr * K + kt * 32 + c4 * 8;
    uint32_t sa = stage_u + (uint32_t)(rr * ASW + c4 * 4) * 4;
    #pragma unroll
    for (int p = 0; p < 4; p++)
        CP_ASYNC16(sa + (uint32_t)(p * 32 * ASW) * 4u, ga + (size_t)(p * 32) * K);
    const uint32_t* gb = Bb2 + (size_t)rr * K2 + kt * 16 + c4 * 4;
    uint32_t sb = stage_u + (uint32_t)(BS_OFF + rr * ASW + c4 * 4) * 4;
    #pragma unroll
    for (int p = 0; p < 4; p++)
        CP_ASYNC16(sb + (uint32_t)(p * 32 * ASW) * 4u, gb + (size_t)(p * 32) * K2);
}

__device__ __forceinline__ void gemm_mainloop(
    uint32_t* sw, const __half* Ab, const uint32_t* Bb2, int K,
    float acc[4][8][4], int tid)
{
    const int lane  = tid & 31;
    const int wid   = tid >> 5;
    const int warpM = wid & 1;
    const int warpN = wid >> 1;
    const int KT = K / 32;
    const uint32_t smem_base = smem_u32(sw);

    #pragma unroll
    for (int s = 0; s < GST - 1; s++) {
        gemm_issue_stage(smem_base + s * STAGE_WORDS * 4, Ab, Bb2, K, s, tid);
        CP_COMMIT();
    }

    const uint32_t aoff = (uint32_t)((warpM * 64 + (lane & 15)) * ASW + (lane >> 4) * 4) * 4;
    const uint32_t boff = (uint32_t)((BS_OFF + (warpN * 64 + (lane & 7) + ((lane >> 4) << 3)) * ASW)
                                     + ((lane >> 3) & 1) * 4) * 4;

    for (int kt = 0; kt < KT; kt++) {
        const int buf = kt & (GST - 1);
        CP_WAIT2();
        __syncthreads();

        const int nxt = kt + GST - 1;
        if (nxt < KT)
            gemm_issue_stage(smem_base + (nxt & (GST - 1)) * STAGE_WORDS * 4,
                             Ab, Bb2, K, nxt, tid);
        CP_COMMIT();

        const uint32_t stage_u = smem_base + buf * STAGE_WORDS * 4;
        #pragma unroll
        for (int ks = 0; ks < 2; ks++) {
            uint32_t af[4][4], bf[8][2];
            #pragma unroll
            for (int mt = 0; mt < 4; mt++)
                ldsm4(af[mt][0], af[mt][1], af[mt][2], af[mt][3],
                      stage_u + aoff + (uint32_t)(mt * 16 * ASW + ks * 8) * 4);
            #pragma unroll
            for (int np = 0; np < 4; np++)
                ldsm4(bf[2*np][0], bf[2*np][1], bf[2*np+1][0], bf[2*np+1][1],
                      stage_u + boff + (uint32_t)(np * 16 * ASW + ks * 8) * 4);
            #pragma unroll
            for (int mt = 0; mt < 4; mt++)
                #pragma unroll
                for (int nt = 0; nt < 8; nt++)
                    mma_f16(acc[mt][nt][0], acc[mt][nt][1], acc[mt][nt][2], acc[mt][nt][3],
                            af[mt][0], af[mt][1], af[mt][2], af[mt][3],
                            bf[nt][0], bf[nt][1]);
        }
        __syncthreads();
    }
}

// ============================================================================
// Fused QKV GEMM: grid (24, 64). x-blocks 0..15 -> q (norm+rope, scaled),
// 16..19 -> k (norm+rope), 20..23 -> v (plain fp16).
// ============================================================================
__global__ __launch_bounds__(128, 2) void qkv_gemm_kernel(
    const __half* __restrict__ A,
    const uint32_t* __restrict__ Wq2, const uint32_t* __restrict__ Wk2,
    const uint32_t* __restrict__ Wv2,
    __half* __restrict__ Qh, __half* __restrict__ Kh, __half* __restrict__ Vg,
    const float* __restrict__ fc)
{
    extern __shared__ uint32_t sw[];
    const int bx  = blockIdx.x;
    const int tid = threadIdx.x;
    const int lane = tid & 31, wid = tid >> 5;
    const int warpM = wid & 1, warpN = wid >> 1;

    const uint32_t* B2;
    __half* Cm;
    int ncol, N;
    bool norm;
    float scale;
    if (bx < 16)      { B2 = Wq2; Cm = Qh; ncol = bx;      N = H_ * D_;   norm = true;  scale = QSCALE; }
    else if (bx < 20) { B2 = Wk2; Cm = Kh; ncol = bx - 16; N = HKV_ * D_; norm = true;  scale = 1.0f; }
    else              { B2 = Wv2; Cm = Vg; ncol = bx - 20; N = HKV_ * D_; norm = false; scale = 1.0f; }

    const __half*   Ab  = A  + (size_t)blockIdx.y * BM * C_;
    const uint32_t* Bb2 = B2 + (size_t)ncol * BN * K2C;

    float acc[4][8][4];
    #pragma unroll
    for (int i = 0; i < 4; i++)
        #pragma unroll
        for (int j = 0; j < 8; j++)
            #pragma unroll
            for (int c = 0; c < 4; c++) acc[i][j][c] = 0.f;

    gemm_mainloop(sw, Ab, Bb2, C_, acc, tid);

    const int r = lane >> 2, c = lane & 3;
    const int ccol0 = warpN * 64 + c * 2;
    __half* Cb = Cm + (size_t)blockIdx.y * BM * N + (size_t)ncol * BN;

    if (!norm) {
        #pragma unroll
        for (int mt = 0; mt < 4; mt++) {
            const int rr = warpM * 64 + mt * 16 + r;
            #pragma unroll
            for (int nt = 0; nt < 8; nt++) {
                const int cc = ccol0 + nt * 8;
                store2(Cb + (size_t)rr * N + cc,       acc[mt][nt][0], acc[mt][nt][1]);
                store2(Cb + (size_t)(rr + 8) * N + cc, acc[mt][nt][2], acc[mt][nt][3]);
            }
        }
        return;
    }

    // --- fused RMSNorm + RoPE epilogue (BN == D == 128: one head per tile) ---
    float* red = (float*)sw;
    #pragma unroll
    for (int mt = 0; mt < 4; mt++) {
        float p0 = 0.f, p1 = 0.f;
        #pragma unroll
        for (int nt = 0; nt < 8; nt++) {
            p0 += acc[mt][nt][0] * acc[mt][nt][0] + acc[mt][nt][1] * acc[mt][nt][1];
            p1 += acc[mt][nt][2] * acc[mt][nt][2] + acc[mt][nt][3] * acc[mt][nt][3];
        }
        p0 += __shfl_xor_sync(0xffffffffu, p0, 1);
        p0 += __shfl_xor_sync(0xffffffffu, p0, 2);
        p1 += __shfl_xor_sync(0xffffffffu, p1, 1);
        p1 += __shfl_xor_sync(0xffffffffu, p1, 2);
        if (c == 0) {
            const int row = warpM * 64 + mt * 16 + r;
            red[warpN * 128 + row]     = p0;
            red[warpN * 128 + row + 8] = p1;
        }
    }
    __syncthreads();

    #pragma unroll
    for (int mt = 0; mt < 4; mt++) {
        const int row0 = warpM * 64 + mt * 16 + r;
        const int row1 = row0 + 8;
        const float ms0 = (red[row0] + red[128 + row0]) * (1.f / (float)D_);
        const float ms1 = (red[row1] + red[128 + row1]) * (1.f / (float)D_);
        const float ri0 = rsqrtf(ms0 + 1e-6f) * scale;
        const float ri1 = rsqrtf(ms1 + 1e-6f) * scale;
        const int t0 = (blockIdx.y * BM + row0) & (T_ - 1);
        const int t1 = (blockIdx.y * BM + row1) & (T_ - 1);
        #pragma unroll
        for (int nt = 0; nt < 8; nt++) {
            const int cc = ccol0 + nt * 8;
            float2 cs0 = *(const float2*)(fc + (size_t)t0 * D_ + cc);
            float2 cs1 = *(const float2*)(fc + (size_t)t1 * D_ + cc);
            float a0 = acc[mt][nt][0], a1 = acc[mt][nt][1];
            float b0 = acc[mt][nt][2], b1 = acc[mt][nt][3];
            store2(Cb + (size_t)row0 * N + cc,
                   (a0 * cs0.x - a1 * cs0.y) * ri0, (a0 * cs0.y + a1 * cs0.x) * ri0);
            store2(Cb + (size_t)row1 * N + cc,
                   (b0 * cs1.x - b1 * cs1.y) * ri1, (b0 * cs1.y + b1 * cs1.x) * ri1);
        }
    }
}

// ============================================================================
// Fused flash-attention + output-projection kernel, 128 threads / CTA
// (2 CTAs/SM). Flash CTAs cover 64 q-rows (4 warps x 16 rows).
// grid = 3072:
//   bid 0..2047   : flash, qt64 = 31 - (bid>>6) (LPT), bh = bid&63.
//   bid 2048..3071: Wc GEMM 128x128, LPT order; waits g_cnt[by]==32.
// ============================================================================
#define QKW 68
#define VSW 36
#define VBUF (128 * VSW)
#define FQ_WORDS (64 * QKW)                                  // 4352
#define FLASH_WORDS (FQ_WORDS + 2 * 64 * QKW + 2 * VBUF)     // 22272 words
#define FLASH_SMEM  (FLASH_WORDS * 4)                        // 89088 B

__global__ __launch_bounds__(128, 2) void flash_wc_kernel(
    const __half* __restrict__ Qh, const __half* __restrict__ Kh,
    const uint32_t* __restrict__ Vt2, __half* __restrict__ Oh,
    const uint32_t* __restrict__ Wc2, float* __restrict__ Out)
{
    extern __shared__ uint32_t sw[];
    const int tid  = threadIdx.x;
    const int lane = tid & 31, wid = tid >> 5;

    if (blockIdx.x < 2048) {
        // ------------------------- flash role (64 q-rows) -------------------------
        const int qt64 = 31 - (int)(blockIdx.x >> 6);   // LPT: heavy first
        const int bh   = blockIdx.x & 63;
        uint32_t* Qs = sw;                       // 64 x 68
        uint32_t* Ks = sw + FQ_WORDS;            // 2 x 64 x 68
        uint32_t* Vs = Ks + 2 * 64 * QKW;        // 2 x 128 x 36

        const int r = lane >> 2, c = lane & 3;
        const int b = bh / H_, h = bh % H_;
        const int kvh = h / REP_;
        const int m0 = qt64 * 64;
        const int wrow = m0 + wid * 16;
        const uint32_t qu = smem_u32(Qs);
        const uint32_t ku = smem_u32(Ks);
        const uint32_t vu = smem_u32(Vs);

        const __half* Qb = Qh + ((size_t)(b * T_ + m0) * H_ + h) * D_;
        const __half* Kb = Kh + ((size_t)b * T_ * HKV_ + kvh) * D_;
        const uint32_t* Vb = Vt2 + (size_t)(b * HKV_ + kvh) * D_ * (T_ / 2);

        for (int i = tid; i < 64 * 16; i += 128) {
            int row = i >> 4, c4 = i & 15;
            CP_ASYNC16(qu + (uint32_t)(row * QKW + c4 * 4) * 4,
                       Qb + (size_t)row * (H_ * D_) + c4 * 8);
            CP_ASYNC16(ku + (uint32_t)(row * QKW + c4 * 4) * 4,
                       Kb + (size_t)row * (HKV_ * D_) + c4 * 8);
        }
        for (int i = tid; i < 128 * 8; i += 128) {
            int row = i >> 3, c4 = i & 7;
            CP_ASYNC16(vu + (uint32_t)(row * VSW + c4 * 4) * 4,
                       Vb + (size_t)row * (T_ / 2) + c4 * 4);
        }
        CP_COMMIT();

        const uint32_t qoff = (uint32_t)((wid * 16 + (lane & 15)) * QKW + (lane >> 4) * 4) * 4;
        const uint32_t koff = (uint32_t)(((lane & 7) + ((lane >> 4) << 3)) * QKW
                                         + ((lane >> 3) & 1) * 4) * 4;
        const uint32_t voff = (uint32_t)(((lane & 7) + ((lane >> 4) << 3)) * VSW
                                         + ((lane >> 3) & 1) * 4) * 4;

        uint32_t qf[8][4];
        float oa[16][4];
        #pragma unroll
        for (int db = 0; db < 16; db++)
            oa[db][0] = oa[db][1] = oa[db][2] = oa[db][3] = 0.f;
        float m0r = -1e30f, m1r = -1e30f, l0 = 0.f, l1 = 0.f;

        const int nT = qt64 + 1;   // 64-key tiles

        for (int j = 0; j < nT; j++) {
            const int buf = j & 1;
            const int n0 = j * 64;
            CP_WAIT0();
            __syncthreads();

            if (j + 1 < nT) {
                const int nb2 = buf ^ 1;
                for (int i = tid; i < 64 * 16; i += 128) {
                    int row = i >> 4, c4 = i & 15;
                    CP_ASYNC16(ku + (uint32_t)(nb2 * 64 * QKW + row * QKW + c4 * 4) * 4,
                               Kb + (size_t)((j + 1) * 64 + row) * (HKV_ * D_) + c4 * 8);
                }
                for (int i = tid; i < 128 * 8; i += 128) {
                    int row = i >> 3, c4 = i & 7;
                    CP_ASYNC16(vu + (uint32_t)(nb2 * VBUF + row * VSW + c4 * 4) * 4,
                               Vb + (size_t)row * (T_ / 2) + (j + 1) * 32 + c4 * 4);
                }
                CP_COMMIT();
            }

            if (j == 0) {
                #pragma unroll
                for (int ks = 0; ks < 8; ks++)
                    ldsm4(qf[ks][0], qf[ks][1], qf[ks][2], qf[ks][3],
                          qu + qoff + (uint32_t)(ks * 8) * 4);
            }

            const uint32_t kbase = ku + (uint32_t)(buf * 64 * QKW) * 4 + koff;
            float s[8][4];
            #pragma unroll
            for (int nb = 0; nb < 8; nb++)
                s[nb][0] = s[nb][1] = s[nb][2] = s[nb][3] = 0.f;
            #pragma unroll
            for (int ks = 0; ks < 8; ks++) {
                uint32_t kf[8][2];
                #pragma unroll
                for (int np = 0; np < 4; np++)
                    ldsm4(kf[2*np][0], kf[2*np][1], kf[2*np+1][0], kf[2*np+1][1],
                          kbase + (uint32_t)(np * 16 * QKW + ks * 8) * 4);
                #pragma unroll
                for (int nb = 0; nb < 8; nb++)
                    mma_f16(s[nb][0], s[nb][1], s[nb][2], s[nb][3],
                            qf[ks][0], qf[ks][1], qf[ks][2], qf[ks][3],
                            kf[nb][0], kf[nb][1]);
            }

            if (n0 + 63 > wrow) {
                #pragma unroll
                for (int nb = 0; nb < 8; nb++) {
                    int col = n0 + nb * 8 + 2 * c;
                    if (col     > wrow + r)     s[nb][0] = -1e30f;
                    if (col + 1 > wrow + r)     s[nb][1] = -1e30f;
                    if (col     > wrow + r + 8) s[nb][2] = -1e30f;
                    if (col + 1 > wrow + r + 8) s[nb][3] = -1e30f;
                }
            }

            float mx0 = -1e30f, mx1 = -1e30f;
            #pragma unroll
            for (int nb = 0; nb < 8; nb++) {
                mx0 = fmaxf(mx0, fmaxf(s[nb][0], s[nb][1]));
                mx1 = fmaxf(mx1, fmaxf(s[nb][2], s[nb][3]));
            }
            mx0 = fmaxf(mx0, __shfl_xor_sync(0xffffffffu, mx0, 1));
            mx0 = fmaxf(mx0, __shfl_xor_sync(0xffffffffu, mx0, 2));
            mx1 = fmaxf(mx1, __shfl_xor_sync(0xffffffffu, mx1, 1));
            mx1 = fmaxf(mx1, __shfl_xor_sync(0xffffffffu, mx1, 2));
            float mn0 = fmaxf(m0r, mx0), mn1 = fmaxf(m1r, mx1);
            float a0 = exp2f(m0r - mn0), a1 = exp2f(m1r - mn1);

            // p = exp2(s - m) in fp16x2 — output IS the PV A-fragment
            uint32_t pf[8][2];
            float ls0 = 0.f, ls1 = 0.f;
            #pragma unroll
            for (int nb = 0; nb < 8; nb++) {
                uint32_t p01 = ex2_f16x2(h2u(__floats2half2_rn(s[nb][0] - mn0, s[nb][1] - mn0)));
                uint32_t p23 = ex2_f16x2(h2u(__floats2half2_rn(s[nb][2] - mn1, s[nb][3] - mn1)));
                pf[nb][0] = p01;
                pf[nb][1] = p23;
                float2 f01 = __half22float2(*(__half2*)&p01);
                float2 f23 = __half22float2(*(__half2*)&p23);
                ls0 += f01.x + f01.y;
                ls1 += f23.x + f23.y;
            }
            ls0 += __shfl_xor_sync(0xffffffffu, ls0, 1);
            ls0 += __shfl_xor_sync(0xffffffffu, ls0, 2);
            ls1 += __shfl_xor_sync(0xffffffffu, ls1, 1);
            ls1 += __shfl_xor_sync(0xffffffffu, ls1, 2);
            l0 = l0 * a0 + ls0; l1 = l1 * a1 + ls1;
            m0r = mn0; m1r = mn1;
            #pragma unroll
            for (int db = 0; db < 16; db++) {
                oa[db][0] *= a0; oa[db][1] *= a0;
                oa[db][2] *= a1; oa[db][3] *= a1;
            }

            const uint32_t vbase = vu + (uint32_t)(buf * VBUF) * 4 + voff;
            #pragma unroll
            for (int kb2 = 0; kb2 < 4; kb2++) {
                uint32_t pa0 = pf[2*kb2][0];
                uint32_t pa1 = pf[2*kb2][1];
                uint32_t pa2 = pf[2*kb2+1][0];
                uint32_t pa3 = pf[2*kb2+1][1];
                #pragma unroll
                for (int dp = 0; dp < 8; dp++) {
                    uint32_t v0, v1, v2, v3;
                    ldsm4(v0, v1, v2, v3,
                          vbase + (uint32_t)(dp * 16 * VSW + kb2 * 8) * 4);
                    mma_f16(oa[2*dp][0], oa[2*dp][1], oa[2*dp][2], oa[2*dp][3],
                            pa0, pa1, pa2, pa3, v0, v1);
                    mma_f16(oa[2*dp+1][0], oa[2*dp+1][1], oa[2*dp+1][2], oa[2*dp+1][3],
                            pa0, pa1, pa2, pa3, v2, v3);
                }
            }
        }

        const float i0 = 1.f / l0, i1 = 1.f / l1;
        const int row_g = m0 + wid * 16 + r;
        __half* Ob = Oh + ((size_t)(b * T_ + row_g) * H_ + h) * D_;
        #pragma unroll
        for (int db = 0; db < 16; db++) {
            *(uint32_t*)(Ob + db * 8 + 2 * c) =
                h2u(__floats2half2_rn(oa[db][0] * i0, oa[db][1] * i0));
            *(uint32_t*)(Ob + (size_t)8 * H_ * D_ + db * 8 + 2 * c) =
                h2u(__floats2half2_rn(oa[db][2] * i1, oa[db][3] * i1));
        }

        __threadfence();
        __syncthreads();
        if (tid == 0) atomicAdd(&g_cnt[b * 16 + (qt64 >> 1)], 1);

    } else {
        // --------- Wc GEMM role: proven 128-thread 128x128 mainloop ---------
        const int wcid = (int)blockIdx.x - 2048;   // 0..1023
        const int qt  = 15 - (wcid >> 6);          // match flash readiness order
        const int rem = wcid & 63;
        const int b   = rem >> 4;
        const int bx  = rem & 15;
        const int by  = b * 16 + qt;

        if (tid == 0) {
            while (atomicAdd(&g_cnt[by], 0) < 32) __nanosleep(256);
        }
        __syncthreads();

        const __half*   Ab  = Oh  + (size_t)by * BM * C_;
        const uint32_t* Bb2 = Wc2 + (size_t)bx * BN * K2C;

        float acc[4][8][4];
        #pragma unroll
        for (int i = 0; i < 4; i++)
            #pragma unroll
            for (int j = 0; j < 8; j++)
                #pragma unroll
                for (int cc = 0; cc < 4; cc++) acc[i][j][cc] = 0.f;

        gemm_mainloop(sw, Ab, Bb2, C_, acc, tid);

        float* Cb = Out + (size_t)by * BM * C_ + (size_t)bx * BN;
        const int r = lane >> 2, c = lane & 3;
        const int warpM = wid & 1, warpN = wid >> 1;
        const int ccol0 = warpN * 64 + c * 2;
        #pragma unroll
        for (int mt = 0; mt < 4; mt++) {
            const int rr = warpM * 64 + mt * 16 + r;
            #pragma unroll
            for (int nt = 0; nt < 8; nt++) {
                const int cc = ccol0 + nt * 8;
                store2(Cb + (size_t)rr * C_ + cc,       acc[mt][nt][0], acc[mt][nt][1]);
                store2(Cb + (size_t)(rr + 8) * C_ + cc, acc[mt][nt][2], acc[mt][nt][3]);
            }
        }
    }
}

// ============================================================================
// Launch
// ============================================================================
extern "C" void kernel_launch(void* const* d_in, const int* in_sizes, int n_in,
                              void* d_out, int out_size)
{
    (void)in_sizes; (void)n_in; (void)out_size;
    const float* x  = (const float*)d_in[0];
    const float* fc = (const float*)d_in[1];
    const float* Wq = (const float*)d_in[2];
    const float* Wk = (const float*)d_in[3];
    const float* Wv = (const float*)d_in[4];
    const float* Wc = (const float*)d_in[5];
    float* out = (float*)d_out;

    __half *xh, *vg, *qh, *kh, *yh;
    uint32_t *vh, *wqt, *wkt, *wvt, *wct;
    cudaGetSymbolAddress((void**)&xh,  g_xh);
    cudaGetSymbolAddress((void**)&vg,  g_vg);
    cudaGetSymbolAddress((void**)&qh,  g_qh);
    cudaGetSymbolAddress((void**)&kh,  g_kh);
    cudaGetSymbolAddress((void**)&vh,  g_vh);
    cudaGetSymbolAddress((void**)&yh,  g_yh);
    cudaGetSymbolAddress((void**)&wqt, g_wqt);
    cudaGetSymbolAddress((void**)&wkt, g_wkt);
    cudaGetSymbolAddress((void**)&wvt, g_wvt);
    cudaGetSymbolAddress((void**)&wct, g_wct);

    // Prep: x conversion + all weight transposes + counter zeroing, one launch
    prep_kernel<<<16384 + 5120, 256>>>(
        (const float4*)x, (uint2*)xh, Wq, Wk, Wv, Wc);

    cudaFuncSetAttribute(qkv_gemm_kernel, cudaFuncAttributeMaxDynamicSharedMemorySize, GEMM_SMEM);
    cudaFuncSetAttribute(flash_wc_kernel, cudaFuncAttributeMaxDynamicSharedMemorySize, FLASH_SMEM);

    // Fused QKV projection + RMSNorm + RoPE epilogue
    qkv_gemm_kernel<<<dim3(24, M_ / BM), 128, GEMM_SMEM>>>(
        xh, wqt, wkt, wvt, qh, kh, vg, fc);

    // V -> [bk][d][t2] half2
    conv_v_kernel<<<(B_ * HKV_ * D_ * (T_/2) + 255) / 256, 256>>>(vg, vh);

    // Fused flash attention + output projection (128-thread CTAs, 2/SM)
    flash_wc_kernel<<<3072, 128, FLASH_SMEM>>>(qh, kh, vh, yh, wct, out);
}